// round 9
// baseline (speedup 1.0000x reference)
#include <cuda_runtime.h>
#include <cuda_fp16.h>
#include <cstdint>

// ---------------- problem constants ----------------
#define M_TOK 4096
#define K_DIM 1024
#define E_NUM 8
#define N_DIM 1024
#define TOPK  2
#define S_TOT (M_TOK * TOPK)
#define SP_MAX 9216
#define NTILES (SP_MAX / 128)           // 72 row tiles

// GEMM tiling
#define BM 128
#define BN 128
#define BK 32
#define KB_ITERS 32                     // 1024 / 32
#define STAGES 4
#define A_STRIDE 80                     // bytes per A smem row (64B data + 16B pad)
#define A_BYTES (BM * A_STRIDE)         // 10240
#define B_BYTES 8192
#define STG_BYTES (A_BYTES + B_BYTES)   // 18432
#define SMEM_TOTAL (STAGES * STG_BYTES) // 73728

// ---------------- device scratch (allocation-free) ----------------
__device__ int   g_tile_e[NTILES];
__device__ int   g_slot_tok[SP_MAX];
__device__ float g_slot_w[SP_MAX];
__device__ int   g_tok_slot[M_TOK * TOPK];
__device__ __align__(128) __half  g_xh [(size_t)SP_MAX * K_DIM];            // gathered x fp16
__device__ __align__(128) __half  g_w1h[(size_t)E_NUM * K_DIM * 2 * N_DIM]; // w1 fp16 [e][k][2n]
__device__ __align__(128) __half  g_w2h[(size_t)E_NUM * N_DIM * K_DIM];     // w2 fp16 [e][n][k]
__device__ __align__(128) __half  g_hh [(size_t)SP_MAX * N_DIM];            // silu(g)*u fp16
__device__ __align__(128) float   g_y  [(size_t)SP_MAX * K_DIM];            // expert outputs fp32

// ---------------- fused routing: one block, 1024 threads ----------------
__global__ __launch_bounds__(1024)
void k_route(const void* __restrict__ ids, const float* __restrict__ tw) {
    __shared__ int s_cnt[E_NUM], s_fill[E_NUM], s_off[E_NUM + 1];
    __shared__ int s_flag;
    const int tid = threadIdx.x;
    if (tid == 0) s_flag = 0;
    if (tid < E_NUM) { s_cnt[tid] = 0; s_fill[tid] = 0; }
    for (int i = tid; i < SP_MAX; i += 1024) g_slot_tok[i] = -1;
    __syncthreads();

    // dtype probe: int64 ids with values 0..7 have all-zero odd 32-bit words
    const int* w32 = (const int*)ids;
    for (int i = tid; i < S_TOT / 2; i += 1024)
        if (w32[2 * i + 1] != 0) s_flag = 1;   // benign race
    __syncthreads();
    const bool is32 = (s_flag != 0);

    for (int i = tid; i < S_TOT; i += 1024) {
        int e = is32 ? w32[i] : (int)((const long long*)ids)[i];
        if (e >= 0 && e < E_NUM) atomicAdd(&s_cnt[e], 1);
    }
    __syncthreads();
    if (tid == 0) {
        int off = 0;
        for (int e = 0; e < E_NUM; e++) { s_off[e] = off; off += (s_cnt[e] + 127) & ~127; }
        s_off[E_NUM] = off;
    }
    __syncthreads();
    if (tid < NTILES) {
        int e = 0;
        for (int x = 0; x < E_NUM; x++)
            if (tid * 128 >= s_off[x] && tid * 128 < s_off[x + 1]) e = x;
        g_tile_e[tid] = e;
    }
    for (int i = tid; i < S_TOT; i += 1024) {
        int e = is32 ? w32[i] : (int)((const long long*)ids)[i];
        if (e >= 0 && e < E_NUM) {
            int pos = s_off[e] + atomicAdd(&s_fill[e], 1);
            g_slot_tok[pos] = i >> 1;        // TOPK = 2
            g_slot_w[pos]   = tw[i];
            g_tok_slot[i]   = pos;
        }
    }
}

// ---------------- conversion pre-pass (both weights, one launch) ----------------
#define W1_N4 (E_NUM * K_DIM * 2 * N_DIM / 4)   // 4M float4
#define W2_N4 (E_NUM * N_DIM * K_DIM / 4)       // 2M float4
__global__ __launch_bounds__(256)
void k_cvt_w(const float* __restrict__ w1, const float* __restrict__ w2,
             __half* __restrict__ o1, __half* __restrict__ o2) {
    int i = blockIdx.x * blockDim.x + threadIdx.x;
    const float* in; __half* out; int idx;
    if (i < W1_N4) { in = w1; out = o1; idx = i; }
    else if (i < W1_N4 + W2_N4) { in = w2; out = o2; idx = i - W1_N4; }
    else return;
    float4 v = ((const float4*)in)[idx];
    ((__half2*)out)[2 * idx]     = __floats2half2_rn(v.x, v.y);
    ((__half2*)out)[2 * idx + 1] = __floats2half2_rn(v.z, v.w);
}

__global__ __launch_bounds__(256) void k_gather_x(const float* __restrict__ x) {
    int slot = blockIdx.x, c = threadIdx.x;
    int tok = g_slot_tok[slot];
    __half2* dst = (__half2*)&g_xh[(size_t)slot * K_DIM];
    if (tok < 0) {
        dst[2 * c]     = __floats2half2_rn(0.f, 0.f);
        dst[2 * c + 1] = __floats2half2_rn(0.f, 0.f);
    } else {
        float4 v = ((const float4*)&x[(size_t)tok * K_DIM])[c];
        dst[2 * c]     = __floats2half2_rn(v.x, v.y);
        dst[2 * c + 1] = __floats2half2_rn(v.z, v.w);
    }
}

// ============ GEMM1 (fused silu): hh[128 x 64] = silu(x@Wg) * (x@Wu) ============
// block: 128 slots x 64 n-cols, dual B (gate & up). 8 warps = 4m x 2n, warp 32x32.
__device__ __forceinline__ void load_stage1(uint32_t sbase, const __half* __restrict__ Ag,
                                            const __half* __restrict__ Bgate,
                                            const __half* __restrict__ Bup,
                                            int kb, int tid) {
    uint32_t As = sbase, Bs = sbase + A_BYTES;
    #pragma unroll
    for (int i = 0; i < 2; i++) {           // A: 512 x 16B chunks
        int idx = tid + i * 256;
        int row = idx >> 2, c = idx & 3;
        uint32_t dst = As + row * A_STRIDE + c * 16;
        const __half* src = Ag + (size_t)row * K_DIM + kb * BK + c * 8;
        asm volatile("cp.async.cg.shared.global [%0], [%1], 16;" :: "r"(dst), "l"(src));
    }
    {                                       // B halves: 256 chunks each, XOR swizzle
        int k = tid >> 3, c = tid & 7;
        uint32_t sw = (uint32_t)((c ^ (k & 7)) * 16);
        size_t goff = (size_t)(kb * BK + k) * (2 * N_DIM) + c * 8;
        asm volatile("cp.async.cg.shared.global [%0], [%1], 16;"
                     :: "r"(Bs + k * 128 + sw), "l"(Bgate + goff));
        asm volatile("cp.async.cg.shared.global [%0], [%1], 16;"
                     :: "r"(Bs + 4096 + k * 128 + sw), "l"(Bup + goff));
    }
}

__global__ __launch_bounds__(256, 2)     // <-- occupancy 2 restored (round-6 fix)
void k_gemm1() {
    extern __shared__ char smem[];
    uint32_t sb;
    asm("{ .reg .u64 t; cvta.to.shared.u64 t, %1; cvt.u32.u64 %0, t; }" : "=r"(sb) : "l"(smem));

    const int tid = threadIdx.x, lane = tid & 31, w = tid >> 5;
    const int wm = w >> 1, wn = w & 1;
    const int slot0 = blockIdx.x * BM, n0 = blockIdx.y * 64;
    const int e = g_tile_e[blockIdx.x];
    const __half* Ag = g_xh + (size_t)slot0 * K_DIM;
    const __half* Bgate = g_w1h + (size_t)e * (K_DIM * 2 * N_DIM) + n0;
    const __half* Bup = Bgate + N_DIM;

    float accg[2][4][4], accu[2][4][4];
    #pragma unroll
    for (int i = 0; i < 2; i++)
        #pragma unroll
        for (int j = 0; j < 4; j++)
            #pragma unroll
            for (int r = 0; r < 4; r++) { accg[i][j][r] = 0.f; accu[i][j][r] = 0.f; }

    const int l15 = lane & 15, l16 = lane >> 4;
    const uint32_t a_off = (uint32_t)(wm * 32 + l15) * A_STRIDE + l16 * 16;
    const int bc_base = wn * 4 + l16;

    #pragma unroll
    for (int p = 0; p < STAGES - 1; p++) {
        load_stage1(sb + p * STG_BYTES, Ag, Bgate, Bup, p, tid);
        asm volatile("cp.async.commit_group;");
    }

    for (int kb = 0; kb < KB_ITERS; kb++) {
        const int s = kb & (STAGES - 1);
        if (kb <= KB_ITERS - 3)      asm volatile("cp.async.wait_group 2;");
        else if (kb == KB_ITERS - 2) asm volatile("cp.async.wait_group 1;");
        else                         asm volatile("cp.async.wait_group 0;");
        __syncthreads();
        if (kb + STAGES - 1 < KB_ITERS) {
            load_stage1(sb + ((kb + STAGES - 1) & (STAGES - 1)) * STG_BYTES,
                        Ag, Bgate, Bup, kb + STAGES - 1, tid);
            asm volatile("cp.async.commit_group;");
        }
        uint32_t As = sb + s * STG_BYTES, Bs = As + A_BYTES;
        #pragma unroll
        for (int kk = 0; kk < 2; kk++) {
            uint32_t a[2][4];
            #pragma unroll
            for (int mt = 0; mt < 2; mt++) {
                uint32_t addr = As + a_off + mt * (16 * A_STRIDE) + kk * 32;
                asm volatile("ldmatrix.sync.aligned.m8n8.x4.shared.b16 {%0,%1,%2,%3}, [%4];"
                    : "=r"(a[mt][0]), "=r"(a[mt][1]), "=r"(a[mt][2]), "=r"(a[mt][3])
                    : "r"(addr));
            }
            uint32_t bg[4][2], bu[4][2];
            const int kq = kk * 16 + l15;
            #pragma unroll
            for (int np = 0; np < 2; np++) {
                int c = bc_base + np * 2;
                uint32_t sw = (uint32_t)((c ^ (kq & 7)) * 16) + kq * 128;
                uint32_t addr = Bs + sw;
                asm volatile("ldmatrix.sync.aligned.m8n8.x4.trans.shared.b16 {%0,%1,%2,%3}, [%4];"
                    : "=r"(bg[2*np][0]), "=r"(bg[2*np][1]), "=r"(bg[2*np+1][0]), "=r"(bg[2*np+1][1])
                    : "r"(addr));
                addr = Bs + 4096 + sw;
                asm volatile("ldmatrix.sync.aligned.m8n8.x4.trans.shared.b16 {%0,%1,%2,%3}, [%4];"
                    : "=r"(bu[2*np][0]), "=r"(bu[2*np][1]), "=r"(bu[2*np+1][0]), "=r"(bu[2*np+1][1])
                    : "r"(addr));
            }
            #pragma unroll
            for (int mt = 0; mt < 2; mt++)
                #pragma unroll
                for (int nt = 0; nt < 4; nt++) {
                    asm volatile("mma.sync.aligned.m16n8k16.row.col.f32.f16.f16.f32 "
                        "{%0,%1,%2,%3}, {%4,%5,%6,%7}, {%8,%9}, {%0,%1,%2,%3};"
                        : "+f"(accg[mt][nt][0]), "+f"(accg[mt][nt][1]),
                          "+f"(accg[mt][nt][2]), "+f"(accg[mt][nt][3])
                        : "r"(a[mt][0]), "r"(a[mt][1]), "r"(a[mt][2]), "r"(a[mt][3]),
                          "r"(bg[nt][0]), "r"(bg[nt][1]));
                    asm volatile("mma.sync.aligned.m16n8k16.row.col.f32.f16.f16.f32 "
                        "{%0,%1,%2,%3}, {%4,%5,%6,%7}, {%8,%9}, {%0,%1,%2,%3};"
                        : "+f"(accu[mt][nt][0]), "+f"(accu[mt][nt][1]),
                          "+f"(accu[mt][nt][2]), "+f"(accu[mt][nt][3])
                        : "r"(a[mt][0]), "r"(a[mt][1]), "r"(a[mt][2]), "r"(a[mt][3]),
                          "r"(bu[nt][0]), "r"(bu[nt][1]));
                }
        }
    }

    // fused silu epilogue: h = silu(gate) * up (fp32 accs), write fp16
    const int g = lane >> 2, tg = lane & 3;
    #pragma unroll
    for (int mt = 0; mt < 2; mt++) {
        const int row = slot0 + wm * 32 + mt * 16 + g;
        #pragma unroll
        for (int nt = 0; nt < 4; nt++) {
            const int col = n0 + wn * 32 + nt * 8 + 2 * tg;
            float gv, h0, h1;
            gv = accg[mt][nt][0]; h0 = gv / (1.f + __expf(-gv)) * accu[mt][nt][0];
            gv = accg[mt][nt][1]; h1 = gv / (1.f + __expf(-gv)) * accu[mt][nt][1];
            *(__half2*)&g_hh[(size_t)row * N_DIM + col] = __floats2half2_rn(h0, h1);
            gv = accg[mt][nt][2]; h0 = gv / (1.f + __expf(-gv)) * accu[mt][nt][2];
            gv = accg[mt][nt][3]; h1 = gv / (1.f + __expf(-gv)) * accu[mt][nt][3];
            *(__half2*)&g_hh[(size_t)(row + 8) * N_DIM + col] = __floats2half2_rn(h0, h1);
        }
    }
}

// ============ GEMM2: y = hh @ w2h[e], block 128x128 (proven) ============
__device__ __forceinline__ void load_stage2(uint32_t sbase, const __half* __restrict__ Ag,
                                            const __half* __restrict__ Bg, int kb, int tid) {
    uint32_t As = sbase, Bs = sbase + A_BYTES;
    #pragma unroll
    for (int i = 0; i < 2; i++) {
        int idx = tid + i * 256;
        int row = idx >> 2, c = idx & 3;
        uint32_t dst = As + row * A_STRIDE + c * 16;
        const __half* src = Ag + (size_t)row * N_DIM + kb * BK + c * 8;
        asm volatile("cp.async.cg.shared.global [%0], [%1], 16;" :: "r"(dst), "l"(src));
    }
    #pragma unroll
    for (int i = 0; i < 2; i++) {
        int idx = tid + i * 256;
        int k = idx >> 4, c = idx & 15;
        uint32_t dst = Bs + k * 256 + ((c ^ (k & 7)) * 16);
        const __half* src = Bg + (size_t)(kb * BK + k) * K_DIM + c * 8;
        asm volatile("cp.async.cg.shared.global [%0], [%1], 16;" :: "r"(dst), "l"(src));
    }
}

__global__ __launch_bounds__(256, 2)
void k_gemm2() {
    extern __shared__ char smem[];
    uint32_t sb;
    asm("{ .reg .u64 t; cvta.to.shared.u64 t, %1; cvt.u32.u64 %0, t; }" : "=r"(sb) : "l"(smem));

    const int tid = threadIdx.x, lane = tid & 31, w = tid >> 5;
    const int wm = w >> 2, wn = w & 3;
    const int slot0 = blockIdx.x * BM, n0 = blockIdx.y * BN;
    const int e = g_tile_e[blockIdx.x];
    const __half* Ag = g_hh + (size_t)slot0 * N_DIM;
    const __half* Bg = g_w2h + (size_t)e * (N_DIM * K_DIM) + n0;

    float acc[4][4][4];
    #pragma unroll
    for (int i = 0; i < 4; i++)
        #pragma unroll
        for (int j = 0; j < 4; j++)
            #pragma unroll
            for (int r = 0; r < 4; r++) acc[i][j][r] = 0.f;

    const int l15 = lane & 15, l16 = lane >> 4;
    const uint32_t a_off = (uint32_t)(wm * 64 + l15) * A_STRIDE + l16 * 16;
    const int bc_base = wn * 4 + l16;

    #pragma unroll
    for (int p = 0; p < STAGES - 1; p++) {
        load_stage2(sb + p * STG_BYTES, Ag, Bg, p, tid);
        asm volatile("cp.async.commit_group;");
    }

    for (int kb = 0; kb < KB_ITERS; kb++) {
        const int s = kb & (STAGES - 1);
        if (kb <= KB_ITERS - 3)      asm volatile("cp.async.wait_group 2;");
        else if (kb == KB_ITERS - 2) asm volatile("cp.async.wait_group 1;");
        else                         asm volatile("cp.async.wait_group 0;");
        __syncthreads();
        if (kb + STAGES - 1 < KB_ITERS) {
            load_stage2(sb + ((kb + STAGES - 1) & (STAGES - 1)) * STG_BYTES,
                        Ag, Bg, kb + STAGES - 1, tid);
            asm volatile("cp.async.commit_group;");
        }
        uint32_t As = sb + s * STG_BYTES, Bs = As + A_BYTES;
        #pragma unroll
        for (int kk = 0; kk < 2; kk++) {
            uint32_t a[4][4];
            #pragma unroll
            for (int mt = 0; mt < 4; mt++) {
                uint32_t addr = As + a_off + mt * (16 * A_STRIDE) + kk * 32;
                asm volatile("ldmatrix.sync.aligned.m8n8.x4.shared.b16 {%0,%1,%2,%3}, [%4];"
                    : "=r"(a[mt][0]), "=r"(a[mt][1]), "=r"(a[mt][2]), "=r"(a[mt][3])
                    : "r"(addr));
            }
            uint32_t b[4][2];
            const int kq = kk * 16 + l15;
            #pragma unroll
            for (int np = 0; np < 2; np++) {
                int c = bc_base + np * 2;
                uint32_t addr = Bs + kq * 256 + ((c ^ (kq & 7)) * 16);
                asm volatile("ldmatrix.sync.aligned.m8n8.x4.trans.shared.b16 {%0,%1,%2,%3}, [%4];"
                    : "=r"(b[2*np][0]), "=r"(b[2*np][1]), "=r"(b[2*np+1][0]), "=r"(b[2*np+1][1])
                    : "r"(addr));
            }
            #pragma unroll
            for (int mt = 0; mt < 4; mt++)
                #pragma unroll
                for (int nt = 0; nt < 4; nt++)
                    asm volatile("mma.sync.aligned.m16n8k16.row.col.f32.f16.f16.f32 "
                        "{%0,%1,%2,%3}, {%4,%5,%6,%7}, {%8,%9}, {%0,%1,%2,%3};"
                        : "+f"(acc[mt][nt][0]), "+f"(acc[mt][nt][1]),
                          "+f"(acc[mt][nt][2]), "+f"(acc[mt][nt][3])
                        : "r"(a[mt][0]), "r"(a[mt][1]), "r"(a[mt][2]), "r"(a[mt][3]),
                          "r"(b[nt][0]), "r"(b[nt][1]));
        }
    }

    const int g = lane >> 2, tg = lane & 3;
    #pragma unroll
    for (int mt = 0; mt < 4; mt++) {
        const int row = slot0 + wm * 64 + mt * 16 + g;
        #pragma unroll
        for (int nt = 0; nt < 4; nt++) {
            const int col = n0 + wn * 32 + nt * 8 + 2 * tg;
            *(float2*)&g_y[(size_t)row * K_DIM + col] =
                make_float2(acc[mt][nt][0], acc[mt][nt][1]);
            *(float2*)&g_y[(size_t)(row + 8) * K_DIM + col] =
                make_float2(acc[mt][nt][2], acc[mt][nt][3]);
        }
    }
}

// ---------------- combine: out[t] = w0*y[s0] + w1*y[s1] ----------------
__global__ __launch_bounds__(256) void k_out(float* __restrict__ out) {
    int t = blockIdx.x;
    int s0 = g_tok_slot[t * TOPK + 0];
    int s1 = g_tok_slot[t * TOPK + 1];
    float w0 = g_slot_w[s0], w1 = g_slot_w[s1];
    const float4* y0 = (const float4*)&g_y[(size_t)s0 * K_DIM];
    const float4* y1 = (const float4*)&g_y[(size_t)s1 * K_DIM];
    float4* o = (float4*)&out[(size_t)t * K_DIM];
    int c = threadIdx.x;
    float4 a = y0[c], b = y1[c];
    o[c] = make_float4(w0 * a.x + w1 * b.x, w0 * a.y + w1 * b.y,
                       w0 * a.z + w1 * b.z, w0 * a.w + w1 * b.w);
}

// ---------------- launch ----------------
extern "C" void kernel_launch(void* const* d_in, const int* in_sizes, int n_in,
                              void* d_out, int out_size) {
    const float* x   = (const float*)d_in[0];
    const float* w1  = (const float*)d_in[1];
    const float* w2  = (const float*)d_in[2];
    const float* tw  = (const float*)d_in[3];
    const void*  ids = d_in[4];
    float* out = (float*)d_out;

    void *p_w1h, *p_w2h;
    cudaGetSymbolAddress(&p_w1h, g_w1h);
    cudaGetSymbolAddress(&p_w2h, g_w2h);

    cudaFuncSetAttribute(k_gemm1, cudaFuncAttributeMaxDynamicSharedMemorySize, SMEM_TOTAL);
    cudaFuncSetAttribute(k_gemm2, cudaFuncAttributeMaxDynamicSharedMemorySize, SMEM_TOTAL);

    // 1: routing (single fused kernel)
    k_route<<<1, 1024>>>(ids, tw);
    // 2: both weight fp16 conversions in one launch
    k_cvt_w<<<(W1_N4 + W2_N4 + 255) / 256, 256>>>(w1, w2, (__half*)p_w1h, (__half*)p_w2h);
    // 3: gather + convert x
    k_gather_x<<<SP_MAX, 256>>>(x);
    // 4: GEMM1 + fused silu  (72 x 16 blocks of 128x64, dual-B, occ 2)
    k_gemm1<<<dim3(NTILES, N_DIM / 64), 256, SMEM_TOTAL>>>();
    // 5: GEMM2 (72 x 8 blocks of 128x128)
    k_gemm2<<<dim3(NTILES, K_DIM / BN), 256, SMEM_TOTAL>>>();
    // 6: combine
    k_out<<<M_TOK, 256>>>(out);
}

// round 10
// speedup vs baseline: 1.0070x; 1.0070x over previous
#include <cuda_runtime.h>
#include <cuda_fp16.h>
#include <cstdint>

// ---------------- problem constants ----------------
#define M_TOK 4096
#define K_DIM 1024
#define E_NUM 8
#define N_DIM 1024
#define TOPK  2
#define S_TOT (M_TOK * TOPK)
#define SP_MAX 9216
#define NTILES (SP_MAX / 128)           // 72 row tiles

// GEMM tiling (round-5 proven)
#define BM 128
#define BN 128
#define BK 32
#define KB_ITERS 32                     // 1024 / 32
#define STAGES 4
#define A_STRIDE 80                     // bytes per A smem row (64B data + 16B pad)
#define A_BYTES (BM * A_STRIDE)         // 10240
#define B_BYTES (BK * 256)              // 8192
#define STG_BYTES (A_BYTES + B_BYTES)   // 18432
#define SMEM_TOTAL (STAGES * STG_BYTES) // 73728

// ---------------- device scratch (allocation-free) ----------------
__device__ int   g_tile_e[NTILES];
__device__ int   g_slot_tok[SP_MAX];
__device__ float g_slot_w[SP_MAX];
__device__ int   g_tok_slot[M_TOK * TOPK];
__device__ __align__(128) __half  g_xh [(size_t)SP_MAX * K_DIM];            // gathered x fp16
__device__ __align__(128) __half  g_w1h[(size_t)E_NUM * K_DIM * 2 * N_DIM]; // w1 fp16 [e][k][2n]
__device__ __align__(128) __half  g_w2h[(size_t)E_NUM * N_DIM * K_DIM];     // w2 fp16 [e][n][k]
__device__ __align__(128) __half  g_gu [(size_t)SP_MAX * 2 * N_DIM];        // gate|up fp16
__device__ __align__(128) __half  g_hh [(size_t)SP_MAX * N_DIM];            // silu(g)*u fp16
__device__ __align__(128) float   g_y  [(size_t)SP_MAX * K_DIM];            // expert outputs fp32

// ---------------- fused routing: one block, 1024 threads ----------------
__global__ __launch_bounds__(1024)
void k_route(const void* __restrict__ ids, const float* __restrict__ tw) {
    __shared__ int s_cnt[E_NUM], s_fill[E_NUM], s_off[E_NUM + 1];
    __shared__ int s_flag;
    const int tid = threadIdx.x;
    if (tid == 0) s_flag = 0;
    if (tid < E_NUM) { s_cnt[tid] = 0; s_fill[tid] = 0; }
    for (int i = tid; i < SP_MAX; i += 1024) g_slot_tok[i] = -1;
    __syncthreads();

    // dtype probe: int64 ids with values 0..7 have all-zero odd 32-bit words
    const int* w32 = (const int*)ids;
    for (int i = tid; i < S_TOT / 2; i += 1024)
        if (w32[2 * i + 1] != 0) s_flag = 1;   // benign race
    __syncthreads();
    const bool is32 = (s_flag != 0);

    for (int i = tid; i < S_TOT; i += 1024) {
        int e = is32 ? w32[i] : (int)((const long long*)ids)[i];
        if (e >= 0 && e < E_NUM) atomicAdd(&s_cnt[e], 1);
    }
    __syncthreads();
    if (tid == 0) {
        int off = 0;
        for (int e = 0; e < E_NUM; e++) { s_off[e] = off; off += (s_cnt[e] + 127) & ~127; }
        s_off[E_NUM] = off;
    }
    __syncthreads();
    if (tid < NTILES) {
        int e = 0;
        for (int x = 0; x < E_NUM; x++)
            if (tid * 128 >= s_off[x] && tid * 128 < s_off[x + 1]) e = x;
        g_tile_e[tid] = e;
    }
    for (int i = tid; i < S_TOT; i += 1024) {
        int e = is32 ? w32[i] : (int)((const long long*)ids)[i];
        if (e >= 0 && e < E_NUM) {
            int pos = s_off[e] + atomicAdd(&s_fill[e], 1);
            g_slot_tok[pos] = i >> 1;        // TOPK = 2
            g_slot_w[pos]   = tw[i];
            g_tok_slot[i]   = pos;
        }
    }
}

// ---------------- conversion pre-pass (both weights, one launch) ----------------
#define W1_N4 (E_NUM * K_DIM * 2 * N_DIM / 4)   // 4M float4
#define W2_N4 (E_NUM * N_DIM * K_DIM / 4)       // 2M float4
__global__ __launch_bounds__(256)
void k_cvt_w(const float* __restrict__ w1, const float* __restrict__ w2,
             __half* __restrict__ o1, __half* __restrict__ o2) {
    int i = blockIdx.x * blockDim.x + threadIdx.x;
    const float* in; __half* out; int idx;
    if (i < W1_N4) { in = w1; out = o1; idx = i; }
    else if (i < W1_N4 + W2_N4) { in = w2; out = o2; idx = i - W1_N4; }
    else return;
    float4 v = ((const float4*)in)[idx];
    ((__half2*)out)[2 * idx]     = __floats2half2_rn(v.x, v.y);
    ((__half2*)out)[2 * idx + 1] = __floats2half2_rn(v.z, v.w);
}

__global__ __launch_bounds__(256) void k_gather_x(const float* __restrict__ x) {
    int slot = blockIdx.x, c = threadIdx.x;   // 256 threads x 4 floats
    int tok = g_slot_tok[slot];
    __half2* dst = (__half2*)&g_xh[(size_t)slot * K_DIM];
    if (tok < 0) {
        dst[2 * c]     = __floats2half2_rn(0.f, 0.f);
        dst[2 * c + 1] = __floats2half2_rn(0.f, 0.f);
    } else {
        float4 v = ((const float4*)&x[(size_t)tok * K_DIM])[c];
        dst[2 * c]     = __floats2half2_rn(v.x, v.y);
        dst[2 * c + 1] = __floats2half2_rn(v.z, v.w);
    }
}

// ---------------- fp16 mma.sync grouped GEMM (round-5 proven) ----------------
// block 128x128, 8 warps (2m x 4n), warp 64x32, BK=32, 4-stage cp.async.
template<int LDB>
__device__ __forceinline__ void load_stage(uint32_t sbase, const __half* __restrict__ Ag,
                                           const __half* __restrict__ Bg, int kb, int tid) {
    uint32_t As = sbase, Bs = sbase + A_BYTES;
    #pragma unroll
    for (int i = 0; i < 2; i++) {           // A: 512 x 16B chunks
        int idx = tid + i * 256;
        int row = idx >> 2, c = idx & 3;
        uint32_t dst = As + row * A_STRIDE + c * 16;
        const __half* src = Ag + (size_t)row * K_DIM + kb * BK + c * 8;
        asm volatile("cp.async.cg.shared.global [%0], [%1], 16;" :: "r"(dst), "l"(src));
    }
    #pragma unroll
    for (int i = 0; i < 2; i++) {           // B: 512 x 16B chunks, XOR swizzle
        int idx = tid + i * 256;
        int k = idx >> 4, c = idx & 15;
        uint32_t dst = Bs + k * 256 + ((c ^ (k & 7)) * 16);
        const __half* src = Bg + (size_t)(kb * BK + k) * LDB + c * 8;
        asm volatile("cp.async.cg.shared.global [%0], [%1], 16;" :: "r"(dst), "l"(src));
    }
}

template<int LDA, int LDB, bool OUT_HALF, int LDOUT>
__global__ __launch_bounds__(256, 2)
void k_mma(const __half* __restrict__ A, const __half* __restrict__ B,
           void* __restrict__ OutV) {
    extern __shared__ char smem[];
    uint32_t sb;
    asm("{ .reg .u64 t; cvta.to.shared.u64 t, %1; cvt.u32.u64 %0, t; }" : "=r"(sb) : "l"(smem));

    const int tid = threadIdx.x, lane = tid & 31, w = tid >> 5;
    const int wm = w >> 2, wn = w & 3;
    const int slot0 = blockIdx.x * BM, n0 = blockIdx.y * BN;
    const int e = g_tile_e[blockIdx.x];
    const __half* Ag = A + (size_t)slot0 * LDA;
    const __half* Bg = B + (size_t)e * ((size_t)LDB * 1024) + n0;

    float acc[4][4][4];
    #pragma unroll
    for (int i = 0; i < 4; i++)
        #pragma unroll
        for (int j = 0; j < 4; j++)
            #pragma unroll
            for (int r = 0; r < 4; r++) acc[i][j][r] = 0.f;

    const int l15 = lane & 15, l16 = lane >> 4;
    const uint32_t a_off = (uint32_t)(wm * 64 + l15) * A_STRIDE + l16 * 16;
    const int bc_base = wn * 4 + l16;     // B chunk base (cols/8)

    // A rows use stride LDA in gmem (K_DIM or N_DIM) — bake into helper via LDB param trick
    #pragma unroll
    for (int p = 0; p < STAGES - 1; p++) {
        // A-part (stride LDA)
        uint32_t As = sb + p * STG_BYTES, Bs = As + A_BYTES;
        #pragma unroll
        for (int i = 0; i < 2; i++) {
            int idx = tid + i * 256;
            int row = idx >> 2, c = idx & 3;
            asm volatile("cp.async.cg.shared.global [%0], [%1], 16;"
                :: "r"(As + row * A_STRIDE + c * 16),
                   "l"(Ag + (size_t)row * LDA + p * BK + c * 8));
        }
        #pragma unroll
        for (int i = 0; i < 2; i++) {
            int idx = tid + i * 256;
            int k = idx >> 4, c = idx & 15;
            asm volatile("cp.async.cg.shared.global [%0], [%1], 16;"
                :: "r"(Bs + k * 256 + ((c ^ (k & 7)) * 16)),
                   "l"(Bg + (size_t)(p * BK + k) * LDB + c * 8));
        }
        asm volatile("cp.async.commit_group;");
    }

    for (int kb = 0; kb < KB_ITERS; kb++) {
        const int s = kb & (STAGES - 1);
        if (kb <= KB_ITERS - 3)      asm volatile("cp.async.wait_group 2;");
        else if (kb == KB_ITERS - 2) asm volatile("cp.async.wait_group 1;");
        else                         asm volatile("cp.async.wait_group 0;");
        __syncthreads();
        if (kb + STAGES - 1 < KB_ITERS) {
            const int p = kb + STAGES - 1;
            uint32_t As = sb + (p & (STAGES - 1)) * STG_BYTES, Bs = As + A_BYTES;
            #pragma unroll
            for (int i = 0; i < 2; i++) {
                int idx = tid + i * 256;
                int row = idx >> 2, c = idx & 3;
                asm volatile("cp.async.cg.shared.global [%0], [%1], 16;"
                    :: "r"(As + row * A_STRIDE + c * 16),
                       "l"(Ag + (size_t)row * LDA + p * BK + c * 8));
            }
            #pragma unroll
            for (int i = 0; i < 2; i++) {
                int idx = tid + i * 256;
                int k = idx >> 4, c = idx & 15;
                asm volatile("cp.async.cg.shared.global [%0], [%1], 16;"
                    :: "r"(Bs + k * 256 + ((c ^ (k & 7)) * 16)),
                       "l"(Bg + (size_t)(p * BK + k) * LDB + c * 8));
            }
            asm volatile("cp.async.commit_group;");
        }
        uint32_t As = sb + s * STG_BYTES, Bs = As + A_BYTES;
        #pragma unroll
        for (int kk = 0; kk < 2; kk++) {
            uint32_t a[4][4];
            #pragma unroll
            for (int mt = 0; mt < 4; mt++) {
                uint32_t addr = As + a_off + mt * (16 * A_STRIDE) + kk * 32;
                asm volatile("ldmatrix.sync.aligned.m8n8.x4.shared.b16 {%0,%1,%2,%3}, [%4];"
                    : "=r"(a[mt][0]), "=r"(a[mt][1]), "=r"(a[mt][2]), "=r"(a[mt][3])
                    : "r"(addr));
            }
            uint32_t b[4][2];
            const int kq = kk * 16 + l15;
            #pragma unroll
            for (int np = 0; np < 2; np++) {
                int c = bc_base + np * 2;
                uint32_t addr = Bs + kq * 256 + ((c ^ (kq & 7)) * 16);
                asm volatile("ldmatrix.sync.aligned.m8n8.x4.trans.shared.b16 {%0,%1,%2,%3}, [%4];"
                    : "=r"(b[2*np][0]), "=r"(b[2*np][1]), "=r"(b[2*np+1][0]), "=r"(b[2*np+1][1])
                    : "r"(addr));
            }
            #pragma unroll
            for (int mt = 0; mt < 4; mt++)
                #pragma unroll
                for (int nt = 0; nt < 4; nt++)
                    asm volatile("mma.sync.aligned.m16n8k16.row.col.f32.f16.f16.f32 "
                        "{%0,%1,%2,%3}, {%4,%5,%6,%7}, {%8,%9}, {%0,%1,%2,%3};"
                        : "+f"(acc[mt][nt][0]), "+f"(acc[mt][nt][1]),
                          "+f"(acc[mt][nt][2]), "+f"(acc[mt][nt][3])
                        : "r"(a[mt][0]), "r"(a[mt][1]), "r"(a[mt][2]), "r"(a[mt][3]),
                          "r"(b[nt][0]), "r"(b[nt][1]));
        }
    }

    // epilogue
    const int g = lane >> 2, tg = lane & 3;
    #pragma unroll
    for (int mt = 0; mt < 4; mt++) {
        const int row = slot0 + wm * 64 + mt * 16 + g;
        #pragma unroll
        for (int nt = 0; nt < 4; nt++) {
            const int col = n0 + wn * 32 + nt * 8 + 2 * tg;
            if (OUT_HALF) {
                __half* o = (__half*)OutV;
                *(__half2*)&o[(size_t)row * LDOUT + col] =
                    __floats2half2_rn(acc[mt][nt][0], acc[mt][nt][1]);
                *(__half2*)&o[(size_t)(row + 8) * LDOUT + col] =
                    __floats2half2_rn(acc[mt][nt][2], acc[mt][nt][3]);
            } else {
                float* o = (float*)OutV;
                *(float2*)&o[(size_t)row * LDOUT + col] =
                    make_float2(acc[mt][nt][0], acc[mt][nt][1]);
                *(float2*)&o[(size_t)(row + 8) * LDOUT + col] =
                    make_float2(acc[mt][nt][2], acc[mt][nt][3]);
            }
        }
    }
}

// ---------------- silu: h = silu(gate) * up ----------------
__global__ __launch_bounds__(128) void k_silu() {
    const int slot = blockIdx.x, c = threadIdx.x;   // 128 threads x 8 elems
    const __half2* gu = (const __half2*)&g_gu[(size_t)slot * (2 * N_DIM)];
    __half2* hh = (__half2*)&g_hh[(size_t)slot * N_DIM];
    #pragma unroll
    for (int i = 0; i < 4; i++) {
        float2 gv = __half22float2(gu[c * 4 + i]);
        float2 uv = __half22float2(gu[N_DIM / 2 + c * 4 + i]);
        float h0 = gv.x / (1.f + __expf(-gv.x)) * uv.x;
        float h1 = gv.y / (1.f + __expf(-gv.y)) * uv.y;
        hh[c * 4 + i] = __floats2half2_rn(h0, h1);
    }
}

// ---------------- combine: out[t] = w0*y[s0] + w1*y[s1] ----------------
__global__ __launch_bounds__(256) void k_out(float* __restrict__ out) {
    int t = blockIdx.x;
    int s0 = g_tok_slot[t * TOPK + 0];
    int s1 = g_tok_slot[t * TOPK + 1];
    float w0 = g_slot_w[s0], w1 = g_slot_w[s1];
    const float4* y0 = (const float4*)&g_y[(size_t)s0 * K_DIM];
    const float4* y1 = (const float4*)&g_y[(size_t)s1 * K_DIM];
    float4* o = (float4*)&out[(size_t)t * K_DIM];
    int c = threadIdx.x;
    float4 a = y0[c], b = y1[c];
    o[c] = make_float4(w0 * a.x + w1 * b.x, w0 * a.y + w1 * b.y,
                       w0 * a.z + w1 * b.z, w0 * a.w + w1 * b.w);
}

// ---------------- launch ----------------
extern "C" void kernel_launch(void* const* d_in, const int* in_sizes, int n_in,
                              void* d_out, int out_size) {
    const float* x   = (const float*)d_in[0];
    const float* w1  = (const float*)d_in[1];
    const float* w2  = (const float*)d_in[2];
    const float* tw  = (const float*)d_in[3];
    const void*  ids = d_in[4];
    float* out = (float*)d_out;

    void *p_xh, *p_w1h, *p_w2h, *p_gu, *p_hh, *p_y;
    cudaGetSymbolAddress(&p_xh, g_xh);
    cudaGetSymbolAddress(&p_w1h, g_w1h);
    cudaGetSymbolAddress(&p_w2h, g_w2h);
    cudaGetSymbolAddress(&p_gu, g_gu);
    cudaGetSymbolAddress(&p_hh, g_hh);
    cudaGetSymbolAddress(&p_y, g_y);

    cudaFuncSetAttribute((const void*)k_mma<K_DIM, 2 * N_DIM, true, 2 * N_DIM>,
                         cudaFuncAttributeMaxDynamicSharedMemorySize, SMEM_TOTAL);
    cudaFuncSetAttribute((const void*)k_mma<N_DIM, K_DIM, false, K_DIM>,
                         cudaFuncAttributeMaxDynamicSharedMemorySize, SMEM_TOTAL);

    // 1: routing (single fused kernel)
    k_route<<<1, 1024>>>(ids, tw);
    // 2: both weight fp16 conversions in one launch
    k_cvt_w<<<(W1_N4 + W2_N4 + 255) / 256, 256>>>(w1, w2, (__half*)p_w1h, (__half*)p_w2h);
    // 3: gather + convert x
    k_gather_x<<<SP_MAX, 256>>>(x);
    // 4: GEMM1: gu = xh @ w1h[e]   (72 x 16 blocks of 128x128)
    k_mma<K_DIM, 2 * N_DIM, true, 2 * N_DIM><<<dim3(NTILES, 2 * N_DIM / BN), 256, SMEM_TOTAL>>>(
        (const __half*)p_xh, (const __half*)p_w1h, p_gu);
    // 5: silu
    k_silu<<<SP_MAX, 128>>>();
    // 6: GEMM2: y = hh @ w2h[e]    (72 x 8 blocks of 128x128)
    k_mma<N_DIM, K_DIM, false, K_DIM><<<dim3(NTILES, K_DIM / BN), 256, SMEM_TOTAL>>>(
        (const __half*)p_hh, (const __half*)p_w2h, p_y);
    // 7: combine
    k_out<<<M_TOK, 256>>>(out);
}

// round 11
// speedup vs baseline: 1.4214x; 1.4115x over previous
#include <cuda_runtime.h>
#include <cuda_fp16.h>
#include <cstdint>

// ---------------- problem constants ----------------
#define M_TOK 4096
#define K_DIM 1024
#define E_NUM 8
#define N_DIM 1024
#define TOPK  2
#define S_TOT (M_TOK * TOPK)
#define SP_MAX 9216
#define NTILES (SP_MAX / 128)           // 72 row tiles

// GEMM tiling
#define BM 128
#define BN 128
#define BK 32
#define KB_ITERS 32                     // 1024 / 32
#define STAGES 4
#define A_STRIDE 80                     // bytes per A smem row (64B data + 16B pad)
#define A_BYTES (BM * A_STRIDE)         // 10240
#define B_BYTES (BK * 256)              // 8192  (128 cols * 2B, swizzled chunks)
#define STG_BYTES (A_BYTES + B_BYTES)   // 18432
#define SMEM_TOTAL (STAGES * STG_BYTES) // 73728

// ---------------- device scratch (allocation-free) ----------------
__device__ int   g_counts[E_NUM];
__device__ int   g_fill[E_NUM];
__device__ int   g_off[E_NUM + 1];
__device__ int   g_tile_e[NTILES];
__device__ int   g_slot_tok[SP_MAX];
__device__ float g_slot_w[SP_MAX];
__device__ int   g_tok_slot[M_TOK * TOPK];
__device__ int   g_odd_nz;
__device__ __align__(128) __half  g_xh [(size_t)SP_MAX * K_DIM];            // gathered x fp16
__device__ __align__(128) __half  g_w1h[(size_t)E_NUM * K_DIM * 2 * N_DIM]; // w1 fp16 [e][k][2n]
__device__ __align__(128) __half  g_w2h[(size_t)E_NUM * N_DIM * K_DIM];     // w2 fp16 [e][n][k]
__device__ __align__(128) __half  g_gu [(size_t)SP_MAX * 2 * N_DIM];        // gate|up fp16
__device__ __align__(128) __half  g_hh [(size_t)SP_MAX * N_DIM];            // silu(g)*u fp16
__device__ __align__(128) float   g_y  [(size_t)SP_MAX * K_DIM];            // expert outputs fp32

// ---------------- dtype probe + routing ----------------
__global__ void k_probe(const int* __restrict__ w) {
    int i = blockIdx.x * blockDim.x + threadIdx.x;
    int idx = 2 * i + 1;
    if (idx < S_TOT && w[idx] != 0) atomicOr(&g_odd_nz, 1);
}
__device__ __forceinline__ int load_id(const void* __restrict__ p, int i) {
    return g_odd_nz ? ((const int*)p)[i] : (int)((const long long*)p)[i];
}
__global__ void k_init() {
    int i = blockIdx.x * blockDim.x + threadIdx.x;
    if (i == 0) g_odd_nz = 0;
    if (i < E_NUM) { g_counts[i] = 0; g_fill[i] = 0; }
    if (i < SP_MAX) g_slot_tok[i] = -1;
}
__global__ void k_count(const void* __restrict__ ids) {
    int i = blockIdx.x * blockDim.x + threadIdx.x;
    if (i < S_TOT) {
        int e = load_id(ids, i);
        if (e >= 0 && e < E_NUM) atomicAdd(&g_counts[e], 1);
    }
}
__global__ void k_off() {
    __shared__ int soff[E_NUM + 1];
    if (threadIdx.x == 0) {
        int off = 0;
        for (int e = 0; e < E_NUM; e++) {
            g_off[e] = off; soff[e] = off;
            off += (g_counts[e] + 127) & ~127;
        }
        g_off[E_NUM] = off; soff[E_NUM] = off;
    }
    __syncthreads();
    int t = threadIdx.x;
    if (t < NTILES) {
        int e = 0;
        for (int x = 0; x < E_NUM; x++)
            if (t * 128 >= soff[x] && t * 128 < soff[x + 1]) e = x;
        g_tile_e[t] = e;
    }
}
__global__ void k_scatter(const void* __restrict__ ids, const float* __restrict__ tw) {
    int i = blockIdx.x * blockDim.x + threadIdx.x;
    if (i < S_TOT) {
        int e = load_id(ids, i);
        if (e >= 0 && e < E_NUM) {
            int pos = g_off[e] + atomicAdd(&g_fill[e], 1);
            g_slot_tok[pos] = i / TOPK;
            g_slot_w[pos]   = tw[i];
            g_tok_slot[i]   = pos;
        }
    }
}

// ---------------- conversion pre-pass ----------------
__global__ __launch_bounds__(256) void k_cvt(const float* __restrict__ in,
                                             __half* __restrict__ out, int n4) {
    int i = blockIdx.x * blockDim.x + threadIdx.x;
    if (i < n4) {
        float4 v = ((const float4*)in)[i];
        ((__half2*)out)[2 * i]     = __floats2half2_rn(v.x, v.y);
        ((__half2*)out)[2 * i + 1] = __floats2half2_rn(v.z, v.w);
    }
}
__global__ __launch_bounds__(256) void k_gather_x(const float* __restrict__ x) {
    int slot = blockIdx.x, c = threadIdx.x;   // 256 threads x 4 floats
    int tok = g_slot_tok[slot];
    __half2* dst = (__half2*)&g_xh[(size_t)slot * K_DIM];
    if (tok < 0) {
        dst[2 * c]     = __floats2half2_rn(0.f, 0.f);
        dst[2 * c + 1] = __floats2half2_rn(0.f, 0.f);
    } else {
        float4 v = ((const float4*)&x[(size_t)tok * K_DIM])[c];
        dst[2 * c]     = __floats2half2_rn(v.x, v.y);
        dst[2 * c + 1] = __floats2half2_rn(v.z, v.w);
    }
}

// ---------------- fp16 mma.sync grouped GEMM ----------------
// block 128x128, 8 warps (2m x 4n), warp 64x32, BK=32, 4-stage cp.async.
template<int LDB>
__device__ __forceinline__ void load_stage(uint32_t sbase, const __half* __restrict__ Ag,
                                           const __half* __restrict__ Bg, int kb, int tid) {
    uint32_t As = sbase, Bs = sbase + A_BYTES;
    #pragma unroll
    for (int i = 0; i < 2; i++) {           // A: 512 x 16B chunks
        int idx = tid + i * 256;
        int row = idx >> 2, c = idx & 3;
        uint32_t dst = As + row * A_STRIDE + c * 16;
        const __half* src = Ag + (size_t)row * K_DIM + kb * BK + c * 8;
        asm volatile("cp.async.cg.shared.global [%0], [%1], 16;" :: "r"(dst), "l"(src));
    }
    #pragma unroll
    for (int i = 0; i < 2; i++) {           // B: 512 x 16B chunks, XOR swizzle
        int idx = tid + i * 256;
        int k = idx >> 4, c = idx & 15;
        uint32_t dst = Bs + k * 256 + ((c ^ (k & 7)) * 16);
        const __half* src = Bg + (size_t)(kb * BK + k) * LDB + c * 8;
        asm volatile("cp.async.cg.shared.global [%0], [%1], 16;" :: "r"(dst), "l"(src));
    }
}

template<int LDB, bool OUT_HALF, int LDOUT>
__global__ __launch_bounds__(256, 2)
void k_mma(const __half* __restrict__ A, const __half* __restrict__ B,
           void* __restrict__ OutV) {
    extern __shared__ char smem[];
    uint32_t sb;
    asm("{ .reg .u64 t; cvta.to.shared.u64 t, %1; cvt.u32.u64 %0, t; }" : "=r"(sb) : "l"(smem));

    const int tid = threadIdx.x, lane = tid & 31, w = tid >> 5;
    const int wm = w >> 2, wn = w & 3;
    const int slot0 = blockIdx.x * BM, n0 = blockIdx.y * BN;
    const int e = g_tile_e[blockIdx.x];
    const __half* Ag = A + (size_t)slot0 * K_DIM;
    const __half* Bg = B + (size_t)e * ((size_t)LDB * 1024) + n0;

    float acc[4][4][4];
    #pragma unroll
    for (int i = 0; i < 4; i++)
        #pragma unroll
        for (int j = 0; j < 4; j++)
            #pragma unroll
            for (int r = 0; r < 4; r++) acc[i][j][r] = 0.f;

    const int l15 = lane & 15, l16 = lane >> 4;
    const uint32_t a_off = (uint32_t)(wm * 64 + l15) * A_STRIDE + l16 * 16;
    const int bc_base = wn * 4 + l16;     // B chunk base (cols/8)

    // prologue: stages 0..2
    #pragma unroll
    for (int p = 0; p < STAGES - 1; p++) {
        load_stage<LDB>(sb + p * STG_BYTES, Ag, Bg, p, tid);
        asm volatile("cp.async.commit_group;");
    }

    for (int kb = 0; kb < KB_ITERS; kb++) {
        const int s = kb & (STAGES - 1);
        if (kb <= KB_ITERS - 3)      asm volatile("cp.async.wait_group 2;");
        else if (kb == KB_ITERS - 2) asm volatile("cp.async.wait_group 1;");
        else                         asm volatile("cp.async.wait_group 0;");
        __syncthreads();
        if (kb + STAGES - 1 < KB_ITERS) {
            load_stage<LDB>(sb + ((kb + STAGES - 1) & (STAGES - 1)) * STG_BYTES,
                            Ag, Bg, kb + STAGES - 1, tid);
            asm volatile("cp.async.commit_group;");
        }
        uint32_t As = sb + s * STG_BYTES, Bs = As + A_BYTES;
        #pragma unroll
        for (int kk = 0; kk < 2; kk++) {
            uint32_t a[4][4];
            #pragma unroll
            for (int mt = 0; mt < 4; mt++) {
                uint32_t addr = As + a_off + mt * (16 * A_STRIDE) + kk * 32;
                asm volatile("ldmatrix.sync.aligned.m8n8.x4.shared.b16 {%0,%1,%2,%3}, [%4];"
                    : "=r"(a[mt][0]), "=r"(a[mt][1]), "=r"(a[mt][2]), "=r"(a[mt][3])
                    : "r"(addr));
            }
            uint32_t b[4][2];
            const int kq = kk * 16 + l15;
            #pragma unroll
            for (int np = 0; np < 2; np++) {
                int c = bc_base + np * 2;
                uint32_t addr = Bs + kq * 256 + ((c ^ (kq & 7)) * 16);
                asm volatile("ldmatrix.sync.aligned.m8n8.x4.trans.shared.b16 {%0,%1,%2,%3}, [%4];"
                    : "=r"(b[2*np][0]), "=r"(b[2*np][1]), "=r"(b[2*np+1][0]), "=r"(b[2*np+1][1])
                    : "r"(addr));
            }
            #pragma unroll
            for (int mt = 0; mt < 4; mt++)
                #pragma unroll
                for (int nt = 0; nt < 4; nt++)
                    asm volatile("mma.sync.aligned.m16n8k16.row.col.f32.f16.f16.f32 "
                        "{%0,%1,%2,%3}, {%4,%5,%6,%7}, {%8,%9}, {%0,%1,%2,%3};"
                        : "+f"(acc[mt][nt][0]), "+f"(acc[mt][nt][1]),
                          "+f"(acc[mt][nt][2]), "+f"(acc[mt][nt][3])
                        : "r"(a[mt][0]), "r"(a[mt][1]), "r"(a[mt][2]), "r"(a[mt][3]),
                          "r"(b[nt][0]), "r"(b[nt][1]));
        }
    }

    // epilogue
    const int g = lane >> 2, tg = lane & 3;
    #pragma unroll
    for (int mt = 0; mt < 4; mt++) {
        const int row = slot0 + wm * 64 + mt * 16 + g;
        #pragma unroll
        for (int nt = 0; nt < 4; nt++) {
            const int col = n0 + wn * 32 + nt * 8 + 2 * tg;
            if (OUT_HALF) {
                __half* o = (__half*)OutV;
                *(__half2*)&o[(size_t)row * LDOUT + col] =
                    __floats2half2_rn(acc[mt][nt][0], acc[mt][nt][1]);
                *(__half2*)&o[(size_t)(row + 8) * LDOUT + col] =
                    __floats2half2_rn(acc[mt][nt][2], acc[mt][nt][3]);
            } else {
                float* o = (float*)OutV;
                *(float2*)&o[(size_t)row * LDOUT + col] =
                    make_float2(acc[mt][nt][0], acc[mt][nt][1]);
                *(float2*)&o[(size_t)(row + 8) * LDOUT + col] =
                    make_float2(acc[mt][nt][2], acc[mt][nt][3]);
            }
        }
    }
}

// ---------------- silu: h = silu(gate) * up ----------------
__global__ __launch_bounds__(128) void k_silu() {
    const int slot = blockIdx.x, c = threadIdx.x;   // 128 threads x 8 elems
    const __half2* gu = (const __half2*)&g_gu[(size_t)slot * (2 * N_DIM)];
    __half2* hh = (__half2*)&g_hh[(size_t)slot * N_DIM];
    #pragma unroll
    for (int i = 0; i < 4; i++) {
        float2 gv = __half22float2(gu[c * 4 + i]);
        float2 uv = __half22float2(gu[N_DIM / 2 + c * 4 + i]);
        float h0 = gv.x / (1.f + __expf(-gv.x)) * uv.x;
        float h1 = gv.y / (1.f + __expf(-gv.y)) * uv.y;
        hh[c * 4 + i] = __floats2half2_rn(h0, h1);
    }
}

// ---------------- combine: out[t] = w0*y[s0] + w1*y[s1] ----------------
__global__ __launch_bounds__(256) void k_out(float* __restrict__ out) {
    int t = blockIdx.x;
    int s0 = g_tok_slot[t * TOPK + 0];
    int s1 = g_tok_slot[t * TOPK + 1];
    float w0 = g_slot_w[s0], w1 = g_slot_w[s1];
    const float4* y0 = (const float4*)&g_y[(size_t)s0 * K_DIM];
    const float4* y1 = (const float4*)&g_y[(size_t)s1 * K_DIM];
    float4* o = (float4*)&out[(size_t)t * K_DIM];
    int c = threadIdx.x;
    float4 a = y0[c], b = y1[c];
    o[c] = make_float4(w0 * a.x + w1 * b.x, w0 * a.y + w1 * b.y,
                       w0 * a.z + w1 * b.z, w0 * a.w + w1 * b.w);
}

// ---------------- launch ----------------
extern "C" void kernel_launch(void* const* d_in, const int* in_sizes, int n_in,
                              void* d_out, int out_size) {
    const float* x   = (const float*)d_in[0];
    const float* w1  = (const float*)d_in[1];
    const float* w2  = (const float*)d_in[2];
    const float* tw  = (const float*)d_in[3];
    const void*  ids = d_in[4];
    float* out = (float*)d_out;

    void *p_xh, *p_w1h, *p_w2h, *p_gu, *p_hh, *p_y;
    cudaGetSymbolAddress(&p_xh, g_xh);
    cudaGetSymbolAddress(&p_w1h, g_w1h);
    cudaGetSymbolAddress(&p_w2h, g_w2h);
    cudaGetSymbolAddress(&p_gu, g_gu);
    cudaGetSymbolAddress(&p_hh, g_hh);
    cudaGetSymbolAddress(&p_y, g_y);

    cudaFuncSetAttribute((const void*)k_mma<2 * N_DIM, true, 2 * N_DIM>,
                         cudaFuncAttributeMaxDynamicSharedMemorySize, SMEM_TOTAL);
    cudaFuncSetAttribute((const void*)k_mma<K_DIM, false, K_DIM>,
                         cudaFuncAttributeMaxDynamicSharedMemorySize, SMEM_TOTAL);

    // routing
    k_init<<<(SP_MAX + 255) / 256, 256>>>();
    k_probe<<<(S_TOT / 2 + 255) / 256, 256>>>((const int*)ids);
    k_count<<<(S_TOT + 255) / 256, 256>>>(ids);
    k_off<<<1, 128>>>();
    k_scatter<<<(S_TOT + 255) / 256, 256>>>(ids, tw);

    // fp16 conversions (w1/w2 independent of routing)
    k_cvt<<<(E_NUM * K_DIM * 2 * N_DIM / 4 + 255) / 256, 256>>>(w1, (__half*)p_w1h,
                                                                E_NUM * K_DIM * 2 * N_DIM / 4);
    k_cvt<<<(E_NUM * N_DIM * K_DIM / 4 + 255) / 256, 256>>>(w2, (__half*)p_w2h,
                                                            E_NUM * N_DIM * K_DIM / 4);
    k_gather_x<<<SP_MAX, 256>>>(x);

    // GEMM1: gu = xh @ w1h[e]   (72 x 16 blocks)
    k_mma<2 * N_DIM, true, 2 * N_DIM><<<dim3(NTILES, 2 * N_DIM / BN), 256, SMEM_TOTAL>>>(
        (const __half*)p_xh, (const __half*)p_w1h, p_gu);
    // silu
    k_silu<<<SP_MAX, 128>>>();
    // GEMM2: y = hh @ w2h[e]    (72 x 8 blocks)
    k_mma<K_DIM, false, K_DIM><<<dim3(NTILES, K_DIM / BN), 256, SMEM_TOTAL>>>(
        (const __half*)p_hh, (const __half*)p_w2h, p_y);
    // combine
    k_out<<<M_TOK, 256>>>(out);
}

// round 13
// speedup vs baseline: 1.4458x; 1.0172x over previous
#include <cuda_runtime.h>
#include <cuda_fp16.h>
#include <cstdint>

// ---------------- problem constants ----------------
#define M_TOK 4096
#define K_DIM 1024
#define E_NUM 8
#define N_DIM 1024
#define TOPK  2
#define S_TOT (M_TOK * TOPK)
#define SP_MAX 9216
#define NTILES (SP_MAX / 128)           // 72 row tiles

// GEMM tiling
#define BM 128
#define BN 128
#define BK 32
#define KB_ITERS 32                     // 1024 / 32
#define STAGES 4
#define A_STRIDE 80                     // bytes per A smem row (64B data + 16B pad)
#define A_BYTES (BM * A_STRIDE)         // 10240
#define B_BYTES (BK * 256)              // 8192  (128 cols * 2B, swizzled chunks)
#define STG_BYTES (A_BYTES + B_BYTES)   // 18432
#define SMEM_TOTAL (STAGES * STG_BYTES) // 73728

// ---------------- device scratch (allocation-free) ----------------
__device__ int   g_tile_e[NTILES];
__device__ int   g_slot_tok[SP_MAX];
__device__ float g_slot_w[SP_MAX];
__device__ int   g_tok_slot[M_TOK * TOPK];
__device__ __align__(128) __half  g_xh [(size_t)SP_MAX * K_DIM];            // gathered x fp16
__device__ __align__(128) __half  g_w1h[(size_t)E_NUM * K_DIM * 2 * N_DIM]; // w1 fp16 [e][k][2n]
__device__ __align__(128) __half  g_w2h[(size_t)E_NUM * N_DIM * K_DIM];     // w2 fp16 [e][n][k]
__device__ __align__(128) __half  g_gu [(size_t)SP_MAX * 2 * N_DIM];        // gate|up fp16
__device__ __align__(128) __half  g_hh [(size_t)SP_MAX * N_DIM];            // silu(g)*u fp16
__device__ __align__(128) float   g_y  [(size_t)SP_MAX * K_DIM];            // expert outputs fp32

// ---------------- fused routing: one block, 1024 threads (proven in R9) ----------------
__global__ __launch_bounds__(1024)
void k_route(const void* __restrict__ ids, const float* __restrict__ tw) {
    __shared__ int s_cnt[E_NUM], s_fill[E_NUM], s_off[E_NUM + 1];
    __shared__ int s_flag;
    const int tid = threadIdx.x;
    if (tid == 0) s_flag = 0;
    if (tid < E_NUM) { s_cnt[tid] = 0; s_fill[tid] = 0; }
    for (int i = tid; i < SP_MAX; i += 1024) g_slot_tok[i] = -1;
    __syncthreads();

    // dtype probe: int64 ids with values 0..7 have all-zero odd 32-bit words
    const int* w32 = (const int*)ids;
    for (int i = tid; i < S_TOT / 2; i += 1024)
        if (w32[2 * i + 1] != 0) s_flag = 1;   // benign race
    __syncthreads();
    const bool is32 = (s_flag != 0);

    for (int i = tid; i < S_TOT; i += 1024) {
        int e = is32 ? w32[i] : (int)((const long long*)ids)[i];
        if (e >= 0 && e < E_NUM) atomicAdd(&s_cnt[e], 1);
    }
    __syncthreads();
    if (tid == 0) {
        int off = 0;
        for (int e = 0; e < E_NUM; e++) { s_off[e] = off; off += (s_cnt[e] + 127) & ~127; }
        s_off[E_NUM] = off;
    }
    __syncthreads();
    if (tid < NTILES) {
        int e = 0;
        for (int x = 0; x < E_NUM; x++)
            if (tid * 128 >= s_off[x] && tid * 128 < s_off[x + 1]) e = x;
        g_tile_e[tid] = e;
    }
    for (int i = tid; i < S_TOT; i += 1024) {
        int e = is32 ? w32[i] : (int)((const long long*)ids)[i];
        if (e >= 0 && e < E_NUM) {
            int pos = s_off[e] + atomicAdd(&s_fill[e], 1);
            g_slot_tok[pos] = i >> 1;        // TOPK = 2
            g_slot_w[pos]   = tw[i];
            g_tok_slot[i]   = pos;
        }
    }
}

// ---------------- conversion pre-pass (both weights, one launch; proven in R9) ----------------
#define W1_N4 (E_NUM * K_DIM * 2 * N_DIM / 4)   // 4M float4
#define W2_N4 (E_NUM * N_DIM * K_DIM / 4)       // 2M float4
__global__ __launch_bounds__(256)
void k_cvt_w(const float* __restrict__ w1, const float* __restrict__ w2,
             __half* __restrict__ o1, __half* __restrict__ o2) {
    int i = blockIdx.x * blockDim.x + threadIdx.x;
    const float* in; __half* out; int idx;
    if (i < W1_N4) { in = w1; out = o1; idx = i; }
    else if (i < W1_N4 + W2_N4) { in = w2; out = o2; idx = i - W1_N4; }
    else return;
    float4 v = ((const float4*)in)[idx];
    ((__half2*)out)[2 * idx]     = __floats2half2_rn(v.x, v.y);
    ((__half2*)out)[2 * idx + 1] = __floats2half2_rn(v.z, v.w);
}

__global__ __launch_bounds__(256) void k_gather_x(const float* __restrict__ x) {
    int slot = blockIdx.x, c = threadIdx.x;   // 256 threads x 4 floats
    int tok = g_slot_tok[slot];
    __half2* dst = (__half2*)&g_xh[(size_t)slot * K_DIM];
    if (tok < 0) {
        dst[2 * c]     = __floats2half2_rn(0.f, 0.f);
        dst[2 * c + 1] = __floats2half2_rn(0.f, 0.f);
    } else {
        float4 v = ((const float4*)&x[(size_t)tok * K_DIM])[c];
        dst[2 * c]     = __floats2half2_rn(v.x, v.y);
        dst[2 * c + 1] = __floats2half2_rn(v.z, v.w);
    }
}

// ---------------- fp16 mma.sync grouped GEMM (IMMUTABLE — proven 242 µs codegen) ----------------
// block 128x128, 8 warps (2m x 4n), warp 64x32, BK=32, 4-stage cp.async.
template<int LDB>
__device__ __forceinline__ void load_stage(uint32_t sbase, const __half* __restrict__ Ag,
                                           const __half* __restrict__ Bg, int kb, int tid) {
    uint32_t As = sbase, Bs = sbase + A_BYTES;
    #pragma unroll
    for (int i = 0; i < 2; i++) {           // A: 512 x 16B chunks
        int idx = tid + i * 256;
        int row = idx >> 2, c = idx & 3;
        uint32_t dst = As + row * A_STRIDE + c * 16;
        const __half* src = Ag + (size_t)row * K_DIM + kb * BK + c * 8;
        asm volatile("cp.async.cg.shared.global [%0], [%1], 16;" :: "r"(dst), "l"(src));
    }
    #pragma unroll
    for (int i = 0; i < 2; i++) {           // B: 512 x 16B chunks, XOR swizzle
        int idx = tid + i * 256;
        int k = idx >> 4, c = idx & 15;
        uint32_t dst = Bs + k * 256 + ((c ^ (k & 7)) * 16);
        const __half* src = Bg + (size_t)(kb * BK + k) * LDB + c * 8;
        asm volatile("cp.async.cg.shared.global [%0], [%1], 16;" :: "r"(dst), "l"(src));
    }
}

template<int LDB, bool OUT_HALF, int LDOUT>
__global__ __launch_bounds__(256, 2)
void k_mma(const __half* __restrict__ A, const __half* __restrict__ B,
           void* __restrict__ OutV) {
    extern __shared__ char smem[];
    uint32_t sb;
    asm("{ .reg .u64 t; cvta.to.shared.u64 t, %1; cvt.u32.u64 %0, t; }" : "=r"(sb) : "l"(smem));

    const int tid = threadIdx.x, lane = tid & 31, w = tid >> 5;
    const int wm = w >> 2, wn = w & 3;
    const int slot0 = blockIdx.x * BM, n0 = blockIdx.y * BN;
    const int e = g_tile_e[blockIdx.x];
    const __half* Ag = A + (size_t)slot0 * K_DIM;
    const __half* Bg = B + (size_t)e * ((size_t)LDB * 1024) + n0;

    float acc[4][4][4];
    #pragma unroll
    for (int i = 0; i < 4; i++)
        #pragma unroll
        for (int j = 0; j < 4; j++)
            #pragma unroll
            for (int r = 0; r < 4; r++) acc[i][j][r] = 0.f;

    const int l15 = lane & 15, l16 = lane >> 4;
    const uint32_t a_off = (uint32_t)(wm * 64 + l15) * A_STRIDE + l16 * 16;
    const int bc_base = wn * 4 + l16;     // B chunk base (cols/8)

    // prologue: stages 0..2
    #pragma unroll
    for (int p = 0; p < STAGES - 1; p++) {
        load_stage<LDB>(sb + p * STG_BYTES, Ag, Bg, p, tid);
        asm volatile("cp.async.commit_group;");
    }

    for (int kb = 0; kb < KB_ITERS; kb++) {
        const int s = kb & (STAGES - 1);
        if (kb <= KB_ITERS - 3)      asm volatile("cp.async.wait_group 2;");
        else if (kb == KB_ITERS - 2) asm volatile("cp.async.wait_group 1;");
        else                         asm volatile("cp.async.wait_group 0;");
        __syncthreads();
        if (kb + STAGES - 1 < KB_ITERS) {
            load_stage<LDB>(sb + ((kb + STAGES - 1) & (STAGES - 1)) * STG_BYTES,
                            Ag, Bg, kb + STAGES - 1, tid);
            asm volatile("cp.async.commit_group;");
        }
        uint32_t As = sb + s * STG_BYTES, Bs = As + A_BYTES;
        #pragma unroll
        for (int kk = 0; kk < 2; kk++) {
            uint32_t a[4][4];
            #pragma unroll
            for (int mt = 0; mt < 4; mt++) {
                uint32_t addr = As + a_off + mt * (16 * A_STRIDE) + kk * 32;
                asm volatile("ldmatrix.sync.aligned.m8n8.x4.shared.b16 {%0,%1,%2,%3}, [%4];"
                    : "=r"(a[mt][0]), "=r"(a[mt][1]), "=r"(a[mt][2]), "=r"(a[mt][3])
                    : "r"(addr));
            }
            uint32_t b[4][2];
            const int kq = kk * 16 + l15;
            #pragma unroll
            for (int np = 0; np < 2; np++) {
                int c = bc_base + np * 2;
                uint32_t addr = Bs + kq * 256 + ((c ^ (kq & 7)) * 16);
                asm volatile("ldmatrix.sync.aligned.m8n8.x4.trans.shared.b16 {%0,%1,%2,%3}, [%4];"
                    : "=r"(b[2*np][0]), "=r"(b[2*np][1]), "=r"(b[2*np+1][0]), "=r"(b[2*np+1][1])
                    : "r"(addr));
            }
            #pragma unroll
            for (int mt = 0; mt < 4; mt++)
                #pragma unroll
                for (int nt = 0; nt < 4; nt++)
                    asm volatile("mma.sync.aligned.m16n8k16.row.col.f32.f16.f16.f32 "
                        "{%0,%1,%2,%3}, {%4,%5,%6,%7}, {%8,%9}, {%0,%1,%2,%3};"
                        : "+f"(acc[mt][nt][0]), "+f"(acc[mt][nt][1]),
                          "+f"(acc[mt][nt][2]), "+f"(acc[mt][nt][3])
                        : "r"(a[mt][0]), "r"(a[mt][1]), "r"(a[mt][2]), "r"(a[mt][3]),
                          "r"(b[nt][0]), "r"(b[nt][1]));
        }
    }

    // epilogue
    const int g = lane >> 2, tg = lane & 3;
    #pragma unroll
    for (int mt = 0; mt < 4; mt++) {
        const int row = slot0 + wm * 64 + mt * 16 + g;
        #pragma unroll
        for (int nt = 0; nt < 4; nt++) {
            const int col = n0 + wn * 32 + nt * 8 + 2 * tg;
            if (OUT_HALF) {
                __half* o = (__half*)OutV;
                *(__half2*)&o[(size_t)row * LDOUT + col] =
                    __floats2half2_rn(acc[mt][nt][0], acc[mt][nt][1]);
                *(__half2*)&o[(size_t)(row + 8) * LDOUT + col] =
                    __floats2half2_rn(acc[mt][nt][2], acc[mt][nt][3]);
            } else {
                float* o = (float*)OutV;
                *(float2*)&o[(size_t)row * LDOUT + col] =
                    make_float2(acc[mt][nt][0], acc[mt][nt][1]);
                *(float2*)&o[(size_t)(row + 8) * LDOUT + col] =
                    make_float2(acc[mt][nt][2], acc[mt][nt][3]);
            }
        }
    }
}

// ---------------- silu: h = silu(gate) * up ----------------
__global__ __launch_bounds__(128) void k_silu() {
    const int slot = blockIdx.x, c = threadIdx.x;   // 128 threads x 8 elems
    const __half2* gu = (const __half2*)&g_gu[(size_t)slot * (2 * N_DIM)];
    __half2* hh = (__half2*)&g_hh[(size_t)slot * N_DIM];
    #pragma unroll
    for (int i = 0; i < 4; i++) {
        float2 gv = __half22float2(gu[c * 4 + i]);
        float2 uv = __half22float2(gu[N_DIM / 2 + c * 4 + i]);
        float h0 = gv.x / (1.f + __expf(-gv.x)) * uv.x;
        float h1 = gv.y / (1.f + __expf(-gv.y)) * uv.y;
        hh[c * 4 + i] = __floats2half2_rn(h0, h1);
    }
}

// ---------------- combine: out[t] = w0*y[s0] + w1*y[s1] ----------------
__global__ __launch_bounds__(256) void k_out(float* __restrict__ out) {
    int t = blockIdx.x;
    int s0 = g_tok_slot[t * TOPK + 0];
    int s1 = g_tok_slot[t * TOPK + 1];
    float w0 = g_slot_w[s0], w1 = g_slot_w[s1];
    const float4* y0 = (const float4*)&g_y[(size_t)s0 * K_DIM];
    const float4* y1 = (const float4*)&g_y[(size_t)s1 * K_DIM];
    float4* o = (float4*)&out[(size_t)t * K_DIM];
    int c = threadIdx.x;
    float4 a = y0[c], b = y1[c];
    o[c] = make_float4(w0 * a.x + w1 * b.x, w0 * a.y + w1 * b.y,
                       w0 * a.z + w1 * b.z, w0 * a.w + w1 * b.w);
}

// ---------------- launch ----------------
extern "C" void kernel_launch(void* const* d_in, const int* in_sizes, int n_in,
                              void* d_out, int out_size) {
    const float* x   = (const float*)d_in[0];
    const float* w1  = (const float*)d_in[1];
    const float* w2  = (const float*)d_in[2];
    const float* tw  = (const float*)d_in[3];
    const void*  ids = d_in[4];
    float* out = (float*)d_out;

    void *p_xh, *p_w1h, *p_w2h, *p_gu, *p_hh, *p_y;
    cudaGetSymbolAddress(&p_xh, g_xh);
    cudaGetSymbolAddress(&p_w1h, g_w1h);
    cudaGetSymbolAddress(&p_w2h, g_w2h);
    cudaGetSymbolAddress(&p_gu, g_gu);
    cudaGetSymbolAddress(&p_hh, g_hh);
    cudaGetSymbolAddress(&p_y, g_y);

    cudaFuncSetAttribute((const void*)k_mma<2 * N_DIM, true, 2 * N_DIM>,
                         cudaFuncAttributeMaxDynamicSharedMemorySize, SMEM_TOTAL);
    cudaFuncSetAttribute((const void*)k_mma<K_DIM, false, K_DIM>,
                         cudaFuncAttributeMaxDynamicSharedMemorySize, SMEM_TOTAL);

    // fork: weight conversion runs concurrently with routing + gather
    cudaStream_t s2;
    cudaStreamCreate(&s2);
    cudaEvent_t ev_fork, ev_join;
    cudaEventCreateWithFlags(&ev_fork, cudaEventDisableTiming);
    cudaEventCreateWithFlags(&ev_join, cudaEventDisableTiming);

    cudaEventRecord(ev_fork, 0);
    cudaStreamWaitEvent(s2, ev_fork, 0);
    k_cvt_w<<<(W1_N4 + W2_N4 + 255) / 256, 256, 0, s2>>>(
        w1, w2, (__half*)p_w1h, (__half*)p_w2h);
    cudaEventRecord(ev_join, s2);

    // main stream: routing + gather (independent of weight conversion)
    k_route<<<1, 1024>>>(ids, tw);
    k_gather_x<<<SP_MAX, 256>>>(x);

    // join before GEMM1 (needs w1h)
    cudaStreamWaitEvent(0, ev_join, 0);

    // GEMM1: gu = xh @ w1h[e]   (72 x 16 blocks)
    k_mma<2 * N_DIM, true, 2 * N_DIM><<<dim3(NTILES, 2 * N_DIM / BN), 256, SMEM_TOTAL>>>(
        (const __half*)p_xh, (const __half*)p_w1h, p_gu);
    // silu
    k_silu<<<SP_MAX, 128>>>();
    // GEMM2: y = hh @ w2h[e]    (72 x 8 blocks)
    k_mma<K_DIM, false, K_DIM><<<dim3(NTILES, K_DIM / BN), 256, SMEM_TOTAL>>>(
        (const __half*)p_hh, (const __half*)p_w2h, p_y);
    // combine
    k_out<<<M_TOK, 256>>>(out);
}